// round 7
// baseline (speedup 1.0000x reference)
#include <cuda_runtime.h>
#include <math.h>

#define NN 65536

__device__ float g_Qk [NN * 512];
__device__ float g_cA [NN * 512];
__device__ float g_h  [NN * 128];
__device__ float g_ff [NN * 256];
__device__ float g_M  [128 * 512];
__device__ float g_WQK[512 * 128];

// ---- packed f32x2 helpers ----
__device__ __forceinline__ unsigned long long pack2(float a, float b) {
    unsigned long long r;
    asm("mov.b64 %0, {%1, %2};" : "=l"(r) : "f"(a), "f"(b));
    return r;
}
__device__ __forceinline__ void fma2(unsigned long long& acc,
                                     unsigned long long a, unsigned long long b) {
    asm("fma.rn.f32x2 %0, %1, %2, %0;" : "+l"(acc) : "l"(a), "l"(b));
}
__device__ __forceinline__ float2 unpack2(unsigned long long v) {
    float2 r;
    asm("mov.b64 {%0, %1}, %2;" : "=f"(r.x), "=f"(r.y) : "l"(v));
    return r;
}
__device__ __forceinline__ float red2(unsigned long long v) {
    float2 p = unpack2(v);
    return p.x + p.y;
}
__device__ __forceinline__ float geluf(float v) {
    return 0.5f * v * (1.0f + erff(v * 0.70710678118654752440f));
}

// M[e, h*128+c] = sum_d Wo[e, h*32+d] * Wv[h*32+d, c]
__global__ void build_m_kernel(const float* __restrict__ Wv,
                               const float* __restrict__ Wo,
                               float* __restrict__ M) {
    __shared__ float wo[128];
    int e = blockIdx.x, c = threadIdx.x;
    wo[c] = Wo[e * 128 + c];
    __syncthreads();
#pragma unroll
    for (int h = 0; h < 4; h++) {
        float a = 0.f;
#pragma unroll
        for (int d = 0; d < 32; d++)
            a = fmaf(wo[h * 32 + d], Wv[(h * 32 + d) * 128 + c], a);
        M[e * 512 + h * 128 + c] = a;
    }
}

// WQK[j=h*128+c, e] = scale * sum_d Wq[h*32+d, e] * Wk[h*32+d, c]
__global__ void build_wqk_kernel(const float* __restrict__ Wq,
                                 const float* __restrict__ Wk,
                                 float* __restrict__ WQK) {
    __shared__ float wk[32];
    int j = blockIdx.x, e = threadIdx.x;
    int h = j >> 7, c = j & 127;
    if (e < 32) wk[e] = Wk[(h * 32 + e) * 128 + c];
    __syncthreads();
    float a = 0.f;
#pragma unroll
    for (int d = 0; d < 32; d++)
        a = fmaf(wk[d], Wq[(h * 32 + d) * 128 + e], a);
    WQK[j * 128 + e] = a * 0.17677669529663687f;
}

// ============================================================================
// Register-tiled GEMM (unchanged from R5)
// ============================================================================
template <int CIN, int COUT_TOTAL, int EPI>
__global__ __launch_bounds__(256, 2) void gemm_rt(
    const float* __restrict__ X, const float* __restrict__ W,
    const float* __restrict__ bias, const float* __restrict__ res,
    const float* __restrict__ gamma, const float* __restrict__ beta,
    float* __restrict__ Y) {
    extern __shared__ float sm[];
    float* Ws = sm;            // [128][64] swizzled f4-units
    float* Xs = sm + 8192;     // [64][68]
    float* Ys = sm;            // [64][132] alias for LN epilogue

    const int tid = threadIdx.x;
    const int tx = tid & 15, ty = tid >> 4;
    const int tx4 = tx * 4, ty4 = ty * 4;
    const int tx7 = tx & 7;
    const int l = tid & 31, w = tid >> 5;
    const int row0 = blockIdx.x * 64;
    const int colofs = blockIdx.y * 128;

    unsigned long long acc2[4][8];
#pragma unroll
    for (int r = 0; r < 4; r++)
#pragma unroll
        for (int c = 0; c < 8; c++) acc2[r][c] = 0ull;

    for (int kc = 0; kc < CIN; kc += 64) {
#pragma unroll
        for (int f = tid; f < 2048; f += 256) {
            int j = f >> 4, q = f & 15;
            ((float4*)Ws)[j * 16 + (q ^ ((j >> 2) & 7))] =
                *(const float4*)&W[(colofs + j) * CIN + kc + q * 4];
        }
#pragma unroll
        for (int f = tid; f < 1024; f += 256) {
            int r = f >> 4, q = f & 15;
            *(float4*)&Xs[r * 68 + q * 4] =
                *(const float4*)&X[(row0 + r) * CIN + kc + q * 4];
        }
        __syncthreads();
#pragma unroll 4
        for (int kk4 = 0; kk4 < 16; kk4++) {
            ulonglong2 xv[4];
#pragma unroll
            for (int r = 0; r < 4; r++)
                xv[r] = *(const ulonglong2*)&Xs[(ty4 + r) * 68 + kk4 * 4];
            const int swofs = kk4 ^ tx7;
#pragma unroll
            for (int g = 0; g < 2; g++)
#pragma unroll
                for (int i = 0; i < 4; i++) {
                    ulonglong2 wv =
                        ((const ulonglong2*)Ws)[(g * 64 + tx4 + i) * 16 + swofs];
                    const int c = g * 4 + i;
#pragma unroll
                    for (int r = 0; r < 4; r++) {
                        fma2(acc2[r][c], xv[r].x, wv.x);
                        fma2(acc2[r][c], xv[r].y, wv.y);
                    }
                }
        }
        __syncthreads();
    }

    if constexpr (EPI <= 1) {
#pragma unroll
        for (int r = 0; r < 4; r++) {
            int gr = row0 + ty4 + r;
#pragma unroll
            for (int g = 0; g < 2; g++) {
                float4 v = make_float4(red2(acc2[r][g * 4 + 0]),
                                       red2(acc2[r][g * 4 + 1]),
                                       red2(acc2[r][g * 4 + 2]),
                                       red2(acc2[r][g * 4 + 3]));
                int cbase = colofs + g * 64 + tx4;
                if constexpr (EPI == 1) {
                    float4 bb = *(const float4*)&bias[cbase];
                    v.x = geluf(v.x + bb.x); v.y = geluf(v.y + bb.y);
                    v.z = geluf(v.z + bb.z); v.w = geluf(v.w + bb.w);
                }
                *(float4*)&Y[gr * COUT_TOTAL + cbase] = v;
            }
        }
    } else {
#pragma unroll
        for (int r = 0; r < 4; r++)
#pragma unroll
            for (int g = 0; g < 2; g++)
                *(float4*)&Ys[(ty4 + r) * 132 + g * 64 + tx4] =
                    make_float4(red2(acc2[r][g * 4 + 0]),
                                red2(acc2[r][g * 4 + 1]),
                                red2(acc2[r][g * 4 + 2]),
                                red2(acc2[r][g * 4 + 3]));
        __syncthreads();
#pragma unroll
        for (int rr = 0; rr < 8; rr++) {
            int r = w * 8 + rr, gr = row0 + r;
            float4 v = *(float4*)&Ys[r * 132 + 4 * l];
            if constexpr (EPI == 3) {
                float4 bb = *(const float4*)&bias[4 * l];
                v.x += bb.x; v.y += bb.y; v.z += bb.z; v.w += bb.w;
            }
            float4 rv = *(const float4*)&res[gr * 128 + 4 * l];
            v.x += rv.x; v.y += rv.y; v.z += rv.z; v.w += rv.w;
            float s1 = v.x + v.y + v.z + v.w;
            float s2 = v.x * v.x + v.y * v.y + v.z * v.z + v.w * v.w;
#pragma unroll
            for (int o = 16; o; o >>= 1) {
                s1 += __shfl_xor_sync(0xffffffffu, s1, o);
                s2 += __shfl_xor_sync(0xffffffffu, s2, o);
            }
            float mean = s1 * (1.f / 128.f);
            float var = s2 * (1.f / 128.f) - mean * mean;
            float inv = rsqrtf(var + 1e-5f);
            float4 g4 = *(const float4*)&gamma[4 * l];
            float4 b4 = *(const float4*)&beta[4 * l];
            float4 o4;
            o4.x = (v.x - mean) * inv * g4.x + b4.x;
            o4.y = (v.y - mean) * inv * g4.y + b4.y;
            o4.z = (v.z - mean) * inv * g4.z + b4.z;
            o4.w = (v.w - mean) * inv * g4.w + b4.w;
            *(float4*)&Y[gr * 128 + 4 * l] = o4;
        }
    }
}

// ============================================================================
// Warp-synchronous attention: warp = node. ctx register-resident for ctxA.
// ============================================================================
__global__ __launch_bounds__(256, 2) void attn_kernel(const float* __restrict__ ctx,
                                                      const float* __restrict__ Qk,
                                                      float* __restrict__ ctxA) {
    extern __shared__ float sm[];
    // per-warp regions
    float* ctxS = sm;                  // 8 x [16][132]
    float* QkS  = sm + 8 * 16 * 132;   // 8 x [512]
    float* sS   = QkS + 8 * 512;       // 8 x [64]
    const int tid = threadIdx.x, l = tid & 31, w = tid >> 5;
    const int n = blockIdx.x * 8 + w;

    float* ctxW = ctxS + w * (16 * 132);
    float* QkW  = QkS + w * 512;
    float* sW   = sS + w * 64;

    // stage: ctx -> regs (lane = c-quad, reg = k) + smem copy; Qk -> smem
    ulonglong2 cr[16];
#pragma unroll
    for (int k = 0; k < 16; k++)
        cr[k] = *(const ulonglong2*)&ctx[(n * 16 + k) * 128 + 4 * l];
#pragma unroll
    for (int t = 0; t < 4; t++)
        *(float4*)&QkW[4 * (t * 32 + l)] =
            *(const float4*)&Qk[n * 512 + 4 * (t * 32 + l)];
#pragma unroll
    for (int k = 0; k < 16; k++)
        *(ulonglong2*)&ctxW[k * 132 + 4 * l] = cr[k];
    __syncwarp();

    // scores: lane -> (k = l&15, hp = l>>4), h = hp + 2*hi
    const int k = l & 15, hp = l >> 4;
    float attn[2];
#pragma unroll
    for (int hi = 0; hi < 2; hi++) {
        const int h = hp + 2 * hi;
        unsigned long long a0 = 0ull, a1 = 0ull;
#pragma unroll
        for (int c = 0; c < 128; c += 4) {
            ulonglong2 q4 = *(const ulonglong2*)&QkW[h * 128 + c];
            ulonglong2 c4 = *(const ulonglong2*)&ctxW[k * 132 + c];
            fma2(a0, q4.x, c4.x);
            fma2(a1, q4.y, c4.y);
        }
        float s = red2(a0) + red2(a1);
        // softmax over the 16-lane k-group (offsets < 16 keep bit4)
        float m = s;
#pragma unroll
        for (int o = 8; o; o >>= 1) m = fmaxf(m, __shfl_xor_sync(0xffffffffu, m, o));
        float e = __expf(s - m);
        float sum = e;
#pragma unroll
        for (int o = 8; o; o >>= 1) sum += __shfl_xor_sync(0xffffffffu, sum, o);
        attn[hi] = e * (1.f / sum);
    }
    sW[(hp + 0) * 16 + k] = attn[0];
    sW[(hp + 2) * 16 + k] = attn[1];
    __syncwarp();

    // ctxA from registers: out[h, 4l..] = sum_k attn[h,k] * cr[k]
#pragma unroll
    for (int h = 0; h < 4; h++) {
        unsigned long long aLo = 0ull, aHi = 0ull;
#pragma unroll
        for (int kk = 0; kk < 16; kk++) {
            float at = sW[h * 16 + kk];           // warp broadcast
            unsigned long long at2 = pack2(at, at);
            fma2(aLo, at2, cr[kk].x);
            fma2(aHi, at2, cr[kk].y);
        }
        float2 pa = unpack2(aLo), pb = unpack2(aHi);
        *(float4*)&ctxA[n * 512 + h * 128 + 4 * l] =
            make_float4(pa.x, pa.y, pb.x, pb.y);
    }
}

extern "C" void kernel_launch(void* const* d_in, const int* in_sizes, int n_in,
                              void* d_out, int out_size) {
    const float* x    = (const float*)d_in[0];
    const float* ctx  = (const float*)d_in[1];
    const float* Wq   = (const float*)d_in[2];
    const float* Wk   = (const float*)d_in[3];
    const float* Wv   = (const float*)d_in[4];
    const float* Wo   = (const float*)d_in[5];
    const float* ln1g = (const float*)d_in[6];
    const float* ln1b = (const float*)d_in[7];
    const float* ln2g = (const float*)d_in[8];
    const float* ln2b = (const float*)d_in[9];
    const float* W1   = (const float*)d_in[10];
    const float* b1   = (const float*)d_in[11];
    const float* W2   = (const float*)d_in[12];
    const float* b2   = (const float*)d_in[13];
    float* out = (float*)d_out;

    float *Qk, *cA, *h, *ff, *M, *WQK;
    cudaGetSymbolAddress((void**)&Qk, g_Qk);
    cudaGetSymbolAddress((void**)&cA, g_cA);
    cudaGetSymbolAddress((void**)&h, g_h);
    cudaGetSymbolAddress((void**)&ff, g_ff);
    cudaGetSymbolAddress((void**)&M, g_M);
    cudaGetSymbolAddress((void**)&WQK, g_WQK);

    const int SM_RT = (128 * 64 + 64 * 68) * 4;                  // 50176
    const int SM_AT = (8 * 16 * 132 + 8 * 512 + 8 * 64) * 4;     // 86016

    static bool attr_done = false;
    if (!attr_done) {
        cudaFuncSetAttribute(gemm_rt<128, 512, 0>,
                             cudaFuncAttributeMaxDynamicSharedMemorySize, SM_RT);
        cudaFuncSetAttribute(gemm_rt<512, 128, 2>,
                             cudaFuncAttributeMaxDynamicSharedMemorySize, SM_RT);
        cudaFuncSetAttribute(gemm_rt<128, 256, 1>,
                             cudaFuncAttributeMaxDynamicSharedMemorySize, SM_RT);
        cudaFuncSetAttribute(gemm_rt<256, 128, 3>,
                             cudaFuncAttributeMaxDynamicSharedMemorySize, SM_RT);
        cudaFuncSetAttribute(attn_kernel,
                             cudaFuncAttributeMaxDynamicSharedMemorySize, SM_AT);
        attr_done = true;
    }

    build_m_kernel<<<128, 128>>>(Wv, Wo, M);
    build_wqk_kernel<<<512, 128>>>(Wq, Wk, WQK);
    gemm_rt<128, 512, 0><<<dim3(NN / 64, 4), 256, SM_RT>>>(
        x, WQK, nullptr, nullptr, nullptr, nullptr, Qk);
    attn_kernel<<<NN / 8, 256, SM_AT>>>(ctx, Qk, cA);
    gemm_rt<512, 128, 2><<<dim3(NN / 64, 1), 256, SM_RT>>>(
        cA, M, nullptr, x, ln1g, ln1b, h);
    gemm_rt<128, 256, 1><<<dim3(NN / 64, 2), 256, SM_RT>>>(
        h, W1, b1, nullptr, nullptr, nullptr, ff);
    gemm_rt<256, 128, 3><<<dim3(NN / 64, 1), 256, SM_RT>>>(
        ff, W2, b2, h, ln2g, ln2b, out);
}

// round 8
// speedup vs baseline: 1.1273x; 1.1273x over previous
#include <cuda_runtime.h>
#include <math.h>

#define NN 65536

__device__ float g_Qk [NN * 512];
__device__ float g_cA [NN * 512];
__device__ float g_h  [NN * 128];
__device__ float g_ff [NN * 256];
__device__ float g_M  [128 * 512];
__device__ float g_WQK[512 * 128];

// ---- packed f32x2 helpers ----
__device__ __forceinline__ unsigned long long pack2(float a, float b) {
    unsigned long long r;
    asm("mov.b64 %0, {%1, %2};" : "=l"(r) : "f"(a), "f"(b));
    return r;
}
__device__ __forceinline__ void fma2(unsigned long long& acc,
                                     unsigned long long a, unsigned long long b) {
    asm("fma.rn.f32x2 %0, %1, %2, %0;" : "+l"(acc) : "l"(a), "l"(b));
}
__device__ __forceinline__ float2 unpack2(unsigned long long v) {
    float2 r;
    asm("mov.b64 {%0, %1}, %2;" : "=f"(r.x), "=f"(r.y) : "l"(v));
    return r;
}
__device__ __forceinline__ float red2(unsigned long long v) {
    float2 p = unpack2(v);
    return p.x + p.y;
}
__device__ __forceinline__ float geluf(float v) {
    return 0.5f * v * (1.0f + erff(v * 0.70710678118654752440f));
}

// M[e, h*128+c] = sum_d Wo[e, h*32+d] * Wv[h*32+d, c]
__global__ void build_m_kernel(const float* __restrict__ Wv,
                               const float* __restrict__ Wo,
                               float* __restrict__ M) {
    __shared__ float wo[128];
    int e = blockIdx.x, c = threadIdx.x;
    wo[c] = Wo[e * 128 + c];
    __syncthreads();
#pragma unroll
    for (int h = 0; h < 4; h++) {
        float a = 0.f;
#pragma unroll
        for (int d = 0; d < 32; d++)
            a = fmaf(wo[h * 32 + d], Wv[(h * 32 + d) * 128 + c], a);
        M[e * 512 + h * 128 + c] = a;
    }
}

// WQK[j=h*128+c, e] = scale * sum_d Wq[h*32+d, e] * Wk[h*32+d, c]
__global__ void build_wqk_kernel(const float* __restrict__ Wq,
                                 const float* __restrict__ Wk,
                                 float* __restrict__ WQK) {
    __shared__ float wk[32];
    int j = blockIdx.x, e = threadIdx.x;
    int h = j >> 7, c = j & 127;
    if (e < 32) wk[e] = Wk[(h * 32 + e) * 128 + c];
    __syncthreads();
    float a = 0.f;
#pragma unroll
    for (int d = 0; d < 32; d++)
        a = fmaf(wk[d], Wq[(h * 32 + d) * 128 + e], a);
    WQK[j * 128 + e] = a * 0.17677669529663687f;
}

// ============================================================================
// Register-tiled GEMM (unchanged — near f32x2 pipe floor)
// ============================================================================
template <int CIN, int COUT_TOTAL, int EPI>
__global__ __launch_bounds__(256, 2) void gemm_rt(
    const float* __restrict__ X, const float* __restrict__ W,
    const float* __restrict__ bias, const float* __restrict__ res,
    const float* __restrict__ gamma, const float* __restrict__ beta,
    float* __restrict__ Y) {
    extern __shared__ float sm[];
    float* Ws = sm;            // [128][64] swizzled f4-units
    float* Xs = sm + 8192;     // [64][68]
    float* Ys = sm;            // [64][132] alias for LN epilogue

    const int tid = threadIdx.x;
    const int tx = tid & 15, ty = tid >> 4;
    const int tx4 = tx * 4, ty4 = ty * 4;
    const int tx7 = tx & 7;
    const int l = tid & 31, w = tid >> 5;
    const int row0 = blockIdx.x * 64;
    const int colofs = blockIdx.y * 128;

    unsigned long long acc2[4][8];
#pragma unroll
    for (int r = 0; r < 4; r++)
#pragma unroll
        for (int c = 0; c < 8; c++) acc2[r][c] = 0ull;

    for (int kc = 0; kc < CIN; kc += 64) {
#pragma unroll
        for (int f = tid; f < 2048; f += 256) {
            int j = f >> 4, q = f & 15;
            ((float4*)Ws)[j * 16 + (q ^ ((j >> 2) & 7))] =
                *(const float4*)&W[(colofs + j) * CIN + kc + q * 4];
        }
#pragma unroll
        for (int f = tid; f < 1024; f += 256) {
            int r = f >> 4, q = f & 15;
            *(float4*)&Xs[r * 68 + q * 4] =
                *(const float4*)&X[(row0 + r) * CIN + kc + q * 4];
        }
        __syncthreads();
#pragma unroll 4
        for (int kk4 = 0; kk4 < 16; kk4++) {
            ulonglong2 xv[4];
#pragma unroll
            for (int r = 0; r < 4; r++)
                xv[r] = *(const ulonglong2*)&Xs[(ty4 + r) * 68 + kk4 * 4];
            const int swofs = kk4 ^ tx7;
#pragma unroll
            for (int g = 0; g < 2; g++)
#pragma unroll
                for (int i = 0; i < 4; i++) {
                    ulonglong2 wv =
                        ((const ulonglong2*)Ws)[(g * 64 + tx4 + i) * 16 + swofs];
                    const int c = g * 4 + i;
#pragma unroll
                    for (int r = 0; r < 4; r++) {
                        fma2(acc2[r][c], xv[r].x, wv.x);
                        fma2(acc2[r][c], xv[r].y, wv.y);
                    }
                }
        }
        __syncthreads();
    }

    if constexpr (EPI <= 1) {
#pragma unroll
        for (int r = 0; r < 4; r++) {
            int gr = row0 + ty4 + r;
#pragma unroll
            for (int g = 0; g < 2; g++) {
                float4 v = make_float4(red2(acc2[r][g * 4 + 0]),
                                       red2(acc2[r][g * 4 + 1]),
                                       red2(acc2[r][g * 4 + 2]),
                                       red2(acc2[r][g * 4 + 3]));
                int cbase = colofs + g * 64 + tx4;
                if constexpr (EPI == 1) {
                    float4 bb = *(const float4*)&bias[cbase];
                    v.x = geluf(v.x + bb.x); v.y = geluf(v.y + bb.y);
                    v.z = geluf(v.z + bb.z); v.w = geluf(v.w + bb.w);
                }
                *(float4*)&Y[gr * COUT_TOTAL + cbase] = v;
            }
        }
    } else {
#pragma unroll
        for (int r = 0; r < 4; r++)
#pragma unroll
            for (int g = 0; g < 2; g++)
                *(float4*)&Ys[(ty4 + r) * 132 + g * 64 + tx4] =
                    make_float4(red2(acc2[r][g * 4 + 0]),
                                red2(acc2[r][g * 4 + 1]),
                                red2(acc2[r][g * 4 + 2]),
                                red2(acc2[r][g * 4 + 3]));
        __syncthreads();
#pragma unroll
        for (int rr = 0; rr < 8; rr++) {
            int r = w * 8 + rr, gr = row0 + r;
            float4 v = *(float4*)&Ys[r * 132 + 4 * l];
            if constexpr (EPI == 3) {
                float4 bb = *(const float4*)&bias[4 * l];
                v.x += bb.x; v.y += bb.y; v.z += bb.z; v.w += bb.w;
            }
            float4 rv = *(const float4*)&res[gr * 128 + 4 * l];
            v.x += rv.x; v.y += rv.y; v.z += rv.z; v.w += rv.w;
            float s1 = v.x + v.y + v.z + v.w;
            float s2 = v.x * v.x + v.y * v.y + v.z * v.z + v.w * v.w;
#pragma unroll
            for (int o = 16; o; o >>= 1) {
                s1 += __shfl_xor_sync(0xffffffffu, s1, o);
                s2 += __shfl_xor_sync(0xffffffffu, s2, o);
            }
            float mean = s1 * (1.f / 128.f);
            float var = s2 * (1.f / 128.f) - mean * mean;
            float inv = rsqrtf(var + 1e-5f);
            float4 g4 = *(const float4*)&gamma[4 * l];
            float4 b4 = *(const float4*)&beta[4 * l];
            float4 o4;
            o4.x = (v.x - mean) * inv * g4.x + b4.x;
            o4.y = (v.y - mean) * inv * g4.y + b4.y;
            o4.z = (v.z - mean) * inv * g4.z + b4.z;
            o4.w = (v.w - mean) * inv * g4.w + b4.w;
            *(float4*)&Y[gr * 128 + 4 * l] = o4;
        }
    }
}

// ============================================================================
// Attention: block-wide coalesced staging (R6), ONE __syncthreads, then
// warp-local scores + shuffle softmax + register-resident ctxA (short liveness)
// ============================================================================
__global__ __launch_bounds__(256, 2) void attn_kernel(const float* __restrict__ ctx,
                                                      const float* __restrict__ Qk,
                                                      float* __restrict__ ctxA) {
    extern __shared__ float sm[];
    float* ctxS = sm;                  // [128][132] (8 nodes x 16 k)
    float* QkS  = sm + 128 * 132;      // [8][512]
    float* sS   = QkS + 8 * 512;       // [8][64]
    const int tid = threadIdx.x, l = tid & 31, w = tid >> 5;
    const int n0 = blockIdx.x * 8;
    const int n = n0 + w;

    // block-wide coalesced staging
#pragma unroll
    for (int f = tid; f < 4096; f += 256) {
        int nn = f >> 9, rem = f & 511, k = rem >> 5, q = rem & 31;
        *(float4*)&ctxS[(nn * 16 + k) * 132 + q * 4] =
            *(const float4*)&ctx[((n0 + nn) * 16 + k) * 128 + q * 4];
    }
#pragma unroll
    for (int f = tid; f < 1024; f += 256) {
        int nn = f >> 7, q = f & 127;
        *(float4*)&QkS[nn * 512 + q * 4] = *(const float4*)&Qk[(n0 + nn) * 512 + q * 4];
    }
    __syncthreads();

    float* ctxW = ctxS + w * (16 * 132);
    float* QkW  = QkS + w * 512;
    float* sW   = sS + w * 64;

    // scores + shuffle softmax: lane -> (k = l&15, hp = l>>4)
    const int k = l & 15, hp = l >> 4;
#pragma unroll
    for (int hi = 0; hi < 2; hi++) {
        const int h = hp + 2 * hi;
        unsigned long long a0 = 0ull, a1 = 0ull;
#pragma unroll
        for (int c = 0; c < 128; c += 4) {
            ulonglong2 q4 = *(const ulonglong2*)&QkW[h * 128 + c];
            ulonglong2 c4 = *(const ulonglong2*)&ctxW[k * 132 + c];
            fma2(a0, q4.x, c4.x);
            fma2(a1, q4.y, c4.y);
        }
        float s = red2(a0) + red2(a1);
        float m = s;
#pragma unroll
        for (int o = 8; o; o >>= 1) m = fmaxf(m, __shfl_xor_sync(0xffffffffu, m, o));
        float e = __expf(s - m);
        float sum = e;
#pragma unroll
        for (int o = 8; o; o >>= 1) sum += __shfl_xor_sync(0xffffffffu, sum, o);
        sW[h * 16 + k] = e * (1.f / sum);
    }
    __syncwarp();

    // ctxA: load node's ctx rows to registers ONCE (short liveness), reuse for 4 heads
    ulonglong2 cr[16];
#pragma unroll
    for (int kk = 0; kk < 16; kk++)
        cr[kk] = *(const ulonglong2*)&ctxW[kk * 132 + 4 * l];
#pragma unroll
    for (int h = 0; h < 4; h++) {
        unsigned long long aLo = 0ull, aHi = 0ull;
#pragma unroll
        for (int kk = 0; kk < 16; kk++) {
            float at = sW[h * 16 + kk];           // warp broadcast
            unsigned long long at2 = pack2(at, at);
            fma2(aLo, at2, cr[kk].x);
            fma2(aHi, at2, cr[kk].y);
        }
        float2 pa = unpack2(aLo), pb = unpack2(aHi);
        *(float4*)&ctxA[n * 512 + h * 128 + 4 * l] =
            make_float4(pa.x, pa.y, pb.x, pb.y);
    }
}

extern "C" void kernel_launch(void* const* d_in, const int* in_sizes, int n_in,
                              void* d_out, int out_size) {
    const float* x    = (const float*)d_in[0];
    const float* ctx  = (const float*)d_in[1];
    const float* Wq   = (const float*)d_in[2];
    const float* Wk   = (const float*)d_in[3];
    const float* Wv   = (const float*)d_in[4];
    const float* Wo   = (const float*)d_in[5];
    const float* ln1g = (const float*)d_in[6];
    const float* ln1b = (const float*)d_in[7];
    const float* ln2g = (const float*)d_in[8];
    const float* ln2b = (const float*)d_in[9];
    const float* W1   = (const float*)d_in[10];
    const float* b1   = (const float*)d_in[11];
    const float* W2   = (const float*)d_in[12];
    const float* b2   = (const float*)d_in[13];
    float* out = (float*)d_out;

    float *Qk, *cA, *h, *ff, *M, *WQK;
    cudaGetSymbolAddress((void**)&Qk, g_Qk);
    cudaGetSymbolAddress((void**)&cA, g_cA);
    cudaGetSymbolAddress((void**)&h, g_h);
    cudaGetSymbolAddress((void**)&ff, g_ff);
    cudaGetSymbolAddress((void**)&M, g_M);
    cudaGetSymbolAddress((void**)&WQK, g_WQK);

    const int SM_RT = (128 * 64 + 64 * 68) * 4;                  // 50176
    const int SM_AT = (128 * 132 + 8 * 512 + 8 * 64) * 4;        // 86016

    static bool attr_done = false;
    if (!attr_done) {
        cudaFuncSetAttribute(gemm_rt<128, 512, 0>,
                             cudaFuncAttributeMaxDynamicSharedMemorySize, SM_RT);
        cudaFuncSetAttribute(gemm_rt<512, 128, 2>,
                             cudaFuncAttributeMaxDynamicSharedMemorySize, SM_RT);
        cudaFuncSetAttribute(gemm_rt<128, 256, 1>,
                             cudaFuncAttributeMaxDynamicSharedMemorySize, SM_RT);
        cudaFuncSetAttribute(gemm_rt<256, 128, 3>,
                             cudaFuncAttributeMaxDynamicSharedMemorySize, SM_RT);
        cudaFuncSetAttribute(attn_kernel,
                             cudaFuncAttributeMaxDynamicSharedMemorySize, SM_AT);
        attr_done = true;
    }

    build_m_kernel<<<128, 128>>>(Wv, Wo, M);
    build_wqk_kernel<<<512, 128>>>(Wq, Wk, WQK);
    gemm_rt<128, 512, 0><<<dim3(NN / 64, 4), 256, SM_RT>>>(
        x, WQK, nullptr, nullptr, nullptr, nullptr, Qk);
    attn_kernel<<<NN / 8, 256, SM_AT>>>(ctx, Qk, cA);
    gemm_rt<512, 128, 2><<<dim3(NN / 64, 1), 256, SM_RT>>>(
        cA, M, nullptr, x, ln1g, ln1b, h);
    gemm_rt<128, 256, 1><<<dim3(NN / 64, 2), 256, SM_RT>>>(
        h, W1, b1, nullptr, nullptr, nullptr, ff);
    gemm_rt<256, 128, 3><<<dim3(NN / 64, 1), 256, SM_RT>>>(
        ff, W2, b2, h, ln2g, ln2b, out);
}